// round 3
// baseline (speedup 1.0000x reference)
#include <cuda_runtime.h>
#include <math.h>

#define TOPK   64
#define MAX_N  262144
#define NBINS  65536
#define NCHUNK 256
#define MAXCAND 4096
#define TPB    512            // 16 warps
#define ROWS_PER_WARP 2       // 32 rows per block

__device__ float        g_alpha[MAX_N];
__device__ unsigned int g_hist[NBINS];     // key >> 16
__device__ unsigned int g_coarse[NCHUNK];  // key >> 24
__device__ unsigned int g_done;            // all zero-init at module load

// order-preserving float -> uint key
__device__ __forceinline__ unsigned int fkey(float f) {
    unsigned int b = __float_as_uint(f);
    return (b & 0x80000000u) ? ~b : (b | 0x80000000u);
}

__global__ void __launch_bounds__(TPB)
fused_kernel(const float* __restrict__ v,
             const float* __restrict__ vs,
             const float* __restrict__ scores,
             float* __restrict__ out, int N) {
    __shared__ float sv[512];
    for (int i = threadIdx.x; i < 512; i += TPB) sv[i] = v[i];
    __syncthreads();

    // ---------------- phase 1: matvec + histograms --------------------------
    int warp = threadIdx.x >> 5;
    int lane = threadIdx.x & 31;
    const int rowsPerBlock = (TPB / 32) * ROWS_PER_WARP;
    int row0 = blockIdx.x * rowsPerBlock + warp * ROWS_PER_WARP;

    const float4* vv4 = (const float4*)sv;
    float4 y0 = vv4[lane +  0];
    float4 y1 = vv4[lane + 32];
    float4 y2 = vv4[lane + 64];
    float4 y3 = vv4[lane + 96];

#pragma unroll
    for (int r = 0; r < ROWS_PER_WARP; r++) {
        int row = row0 + r;
        if (row < N) {
            const float4* p = (const float4*)(vs + (size_t)row * 512);
            float4 x0 = p[lane +  0];
            float4 x1 = p[lane + 32];
            float4 x2 = p[lane + 64];
            float4 x3 = p[lane + 96];
            float acc = x0.x*y0.x + x0.y*y0.y + x0.z*y0.z + x0.w*y0.w
                      + x1.x*y1.x + x1.y*y1.y + x1.z*y1.z + x1.w*y1.w
                      + x2.x*y2.x + x2.y*y2.y + x2.z*y2.z + x2.w*y2.w
                      + x3.x*y3.x + x3.y*y3.y + x3.z*y3.z + x3.w*y3.w;
#pragma unroll
            for (int o = 16; o; o >>= 1) acc += __shfl_xor_sync(0xffffffffu, acc, o);
            if (lane == 0) {
                g_alpha[row] = acc;
                unsigned int k = fkey(acc);
                atomicAdd(&g_hist[k >> 16], 1u);
                atomicAdd(&g_coarse[k >> 24], 1u);
            }
        }
    }

    // ---------------- last-block election ------------------------------------
    __shared__ unsigned int s_isLast;
    __threadfence();
    __syncthreads();
    if (threadIdx.x == 0)
        s_isLast = (atomicAdd(&g_done, 1u) == gridDim.x - 1) ? 1u : 0u;
    __syncthreads();
    if (!s_isLast) return;
    __threadfence();

    // ---------------- phase 2: threshold bin ---------------------------------
    __shared__ unsigned int sc[NCHUNK];
    __shared__ unsigned int sf[256];
    __shared__ unsigned int s_tb;
    if (threadIdx.x < NCHUNK) sc[threadIdx.x] = g_coarse[threadIdx.x];
    __syncthreads();

    __shared__ int s_chunk;
    __shared__ unsigned int s_above;
    if (threadIdx.x == 0) {
        unsigned int cum = 0;
        int c;
        for (c = 255; c >= 0; c--) {
            if (cum + sc[c] >= (unsigned int)TOPK) break;
            cum += sc[c];
        }
        if (c < 0) c = 0;
        s_chunk = c;
        s_above = cum;
    }
    __syncthreads();
    if (threadIdx.x < 256) sf[threadIdx.x] = g_hist[s_chunk * 256 + threadIdx.x];
    __syncthreads();
    if (threadIdx.x == 0) {
        unsigned int cum = s_above;
        int b;
        for (b = 255; b >= 0; b--) {
            cum += sf[b];
            if (cum >= (unsigned int)TOPK) break;
        }
        if (b < 0) b = 0;
        s_tb = (unsigned int)(s_chunk * 256 + b);
    }
    __syncthreads();
    unsigned int tb = s_tb;

    // ---------------- phase 3: scan alpha, select candidates into smem -------
    __shared__ float sval[MAXCAND];
    __shared__ int   sidx[MAXCAND];
    __shared__ int   s_cand;
    if (threadIdx.x == 0) s_cand = 0;
    __syncthreads();

    int n4 = N >> 2;
    for (int i = threadIdx.x; i < n4; i += TPB) {
        float4 a = ((const float4*)g_alpha)[i];
        int base = i << 2;
        if ((fkey(a.x) >> 16) >= tb) {
            int p = atomicAdd(&s_cand, 1);
            if (p < MAXCAND) { sval[p] = a.x; sidx[p] = base + 0; }
        }
        if ((fkey(a.y) >> 16) >= tb) {
            int p = atomicAdd(&s_cand, 1);
            if (p < MAXCAND) { sval[p] = a.y; sidx[p] = base + 1; }
        }
        if ((fkey(a.z) >> 16) >= tb) {
            int p = atomicAdd(&s_cand, 1);
            if (p < MAXCAND) { sval[p] = a.z; sidx[p] = base + 2; }
        }
        if ((fkey(a.w) >> 16) >= tb) {
            int p = atomicAdd(&s_cand, 1);
            if (p < MAXCAND) { sval[p] = a.w; sidx[p] = base + 3; }
        }
    }
    if (threadIdx.x == 0) {
        for (int i = n4 << 2; i < N; i++) {
            float a = g_alpha[i];
            if ((fkey(a) >> 16) >= tb) {
                int p = atomicAdd(&s_cand, 1);
                if (p < MAXCAND) { sval[p] = a; sidx[p] = i; }
            }
        }
    }
    __syncthreads();
    int C = s_cand;
    if (C > MAXCAND) C = MAXCAND;

    // ---------------- phase 4: max, rank-select, softmax, weighted sum -------
    __shared__ float r1[TPB];
    __shared__ float r2[TPB];

    float m = -INFINITY;
    for (int i = threadIdx.x; i < C; i += TPB) m = fmaxf(m, sval[i]);
    r1[threadIdx.x] = m;
    __syncthreads();
    for (int s = TPB / 2; s; s >>= 1) {
        if (threadIdx.x < s) r1[threadIdx.x] = fmaxf(r1[threadIdx.x], r1[threadIdx.x + s]);
        __syncthreads();
    }
    m = r1[0];
    __syncthreads();

    float se = 0.f, acc = 0.f;
    for (int i = threadIdx.x; i < C; i += TPB) {
        float vi = sval[i];
        unsigned int ki = fkey(vi);
        int rank = 0;
        for (int j = 0; j < C; j++) {
            unsigned int kj = fkey(sval[j]);
            rank += (kj > ki) || (kj == ki && j < i);
        }
        if (rank < TOPK) {
            float e = __expf(vi - m);
            se += e;
            acc += e * scores[sidx[i]];
        }
    }
    r1[threadIdx.x] = se;
    r2[threadIdx.x] = acc;
    __syncthreads();
    for (int s = TPB / 2; s; s >>= 1) {
        if (threadIdx.x < s) {
            r1[threadIdx.x] += r1[threadIdx.x + s];
            r2[threadIdx.x] += r2[threadIdx.x + s];
        }
        __syncthreads();
    }
    if (threadIdx.x == 0) out[0] = r2[0] / r1[0];

    // ---------------- phase 5: reset scratch for next graph replay -----------
    // zero only fine-hist chunks that were touched (coarse[c] != 0), then coarse.
    if (threadIdx.x < NCHUNK) {
        if (sc[threadIdx.x] != 0u) {
            uint4 z = make_uint4(0u, 0u, 0u, 0u);
            uint4* dst = (uint4*)&g_hist[threadIdx.x * 256];
#pragma unroll
            for (int j = 0; j < 64; j++) dst[j] = z;
        }
        g_coarse[threadIdx.x] = 0u;
    }
    if (threadIdx.x == 0) g_done = 0u;
}

// ---------------- launch ------------------------------------------------------
extern "C" void kernel_launch(void* const* d_in, const int* in_sizes, int n_in,
                              void* d_out, int out_size) {
    const float* v      = (const float*)d_in[0];
    const float* vs     = (const float*)d_in[1];
    const float* scores = (const float*)d_in[2];
    float* out = (float*)d_out;
    int N = in_sizes[2];
    (void)n_in; (void)out_size;

    const int rowsPerBlock = (TPB / 32) * ROWS_PER_WARP;   // 32
    int blocks = (N + rowsPerBlock - 1) / rowsPerBlock;
    fused_kernel<<<blocks, TPB>>>(v, vs, scores, out, N);
}